// round 3
// baseline (speedup 1.0000x reference)
#include <cuda_runtime.h>
#include <cstddef>

// Problem constants (fixed by the dataset: B=2, N=50000, D=16)
#define MAXB 2
#define MAXN 50000

// Packed coordinates: for point t, g_pack[2t] = {x1,y1,z1,0}, g_pack[2t+1] = {x2,y2,z2,0}.
// Interleaved so both gathers for a neighbor hit the same 32B segment / 128B line.
__device__ float4 g_pack[2 * MAXB * MAXN];

// FMA-pipe inverse sqrt (keeps MUFU idle in the hot Jacobi loop).
// 2 Newton steps: max rel err ~5e-6.
__device__ __forceinline__ float frsqrt_fast(float x) {
    float xh = 0.5f * x;
    float y = __int_as_float(0x5f3759df - (__float_as_int(x) >> 1));
    y = y * (1.5f - xh * y * y);
    y = y * (1.5f - xh * y * y);
    return y;
}

// ---------------------------------------------------------------------------
// Pre-pass: float3 AoS -> interleaved float4 pairs
// ---------------------------------------------------------------------------
__global__ void pack_kernel(const float* __restrict__ xyz1,
                            const float* __restrict__ xyz2, int npts) {
    int t = blockIdx.x * blockDim.x + threadIdx.x;
    if (t >= npts) return;
    float ax = xyz1[3 * t + 0], ay = xyz1[3 * t + 1], az = xyz1[3 * t + 2];
    float cx = xyz2[3 * t + 0], cy = xyz2[3 * t + 1], cz = xyz2[3 * t + 2];
    g_pack[2 * t + 0] = make_float4(ax, ay, az, 0.f);
    g_pack[2 * t + 1] = make_float4(cx, cy, cz, 0.f);
}

// ---------------------------------------------------------------------------
// One Jacobi conjugation on symmetric K with approximate-Givens quaternion
// (McAdams et al.), accumulating the rotation into V. p,q compile-time so
// all array indexing constant-folds into registers.
// ---------------------------------------------------------------------------
template <int p, int q>
__device__ __forceinline__ void jrot(float K[3][3], float V[3][3]) {
    constexpr int r = 3 - p - q;
    float kpq = K[p][q];
    float ch = 2.f * (K[p][p] - K[q][q]);
    float sh = kpq;
    bool use = (5.82842712474619f * sh * sh) < (ch * ch);  // gamma = 3 + 2*sqrt(2)
    float w = frsqrt_fast(fmaf(ch, ch, sh * sh));
    ch = use ? w * ch : 0.92387953251f;  // cos(pi/8)
    sh = use ? w * sh : 0.38268343236f;  // sin(pi/8)
    float c = ch * ch - sh * sh;
    float s = 2.f * sh * ch;

    float kpp = K[p][p], kqq = K[q][q], kpr = K[p][r], kqr = K[q][r];
    float cc = c * c, ss = s * s, cs = c * s;
    K[p][p] = cc * kpp + 2.f * cs * kpq + ss * kqq;
    K[q][q] = ss * kpp - 2.f * cs * kpq + cc * kqq;
    float npq = cs * (kqq - kpp) + (cc - ss) * kpq;
    K[p][q] = npq; K[q][p] = npq;
    float npr = c * kpr + s * kqr;
    float nqr = fmaf(-s, kpr, c * kqr);
    K[p][r] = npr; K[r][p] = npr;
    K[q][r] = nqr; K[r][q] = nqr;

#pragma unroll
    for (int t = 0; t < 3; t++) {
        float vp = V[t][p], vq = V[t][q];
        V[t][p] = fmaf(c, vp, s * vq);
        V[t][q] = fmaf(-s, vp, c * vq);
    }
}

// ---------------------------------------------------------------------------
// Main kernel: one thread per (batch, vertex).
// ---------------------------------------------------------------------------
__global__ __launch_bounds__(256, 2) void arap_rot_kernel(
    const int* __restrict__ nbr, const int* __restrict__ numN,
    const int* __restrict__ accN, const float* __restrict__ wgt,
    float* __restrict__ out, int n) {
    int i = blockIdx.x * blockDim.x + threadIdx.x;
    int b = blockIdx.y;
    if (i >= n) return;
    int vbase = b * n;

    const float4* __restrict__ pk = g_pack;
    float4 p1 = pk[2 * (vbase + i) + 0];
    float4 p2 = pk[2 * (vbase + i) + 1];

    float S00 = 0.f, S01 = 0.f, S02 = 0.f;
    float S10 = 0.f, S11 = 0.f, S12 = 0.f;
    float S20 = 0.f, S21 = 0.f, S22 = 0.f;

    int start = accN[i];
    int cnt = numN[i];

    auto accum = [&](int j, float wv) {
        float4 q1 = pk[2 * (vbase + j) + 0];
        float4 q2 = pk[2 * (vbase + j) + 1];
        float d1x = p1.x - q1.x, d1y = p1.y - q1.y, d1z = p1.z - q1.z;
        float d2x = p2.x - q2.x, d2y = p2.y - q2.y, d2z = p2.z - q2.z;
        float wx = wv * d1x, wy = wv * d1y, wz = wv * d1z;
        S00 = fmaf(wx, d2x, S00); S01 = fmaf(wx, d2y, S01); S02 = fmaf(wx, d2z, S02);
        S10 = fmaf(wy, d2x, S10); S11 = fmaf(wy, d2y, S11); S12 = fmaf(wy, d2z, S12);
        S20 = fmaf(wz, d2x, S20); S21 = fmaf(wz, d2y, S21); S22 = fmaf(wz, d2z, S22);
    };

    if (cnt == 16 && (start & 3) == 0) {
        const int4* n4 = (const int4*)(nbr + start);
        const float4* w4 = (const float4*)(wgt + start);
#pragma unroll
        for (int a = 0; a < 4; a++) {
            int4 nn = n4[a];
            float4 ww = w4[a];
            accum(nn.x, ww.x);
            accum(nn.y, ww.y);
            accum(nn.z, ww.z);
            accum(nn.w, ww.w);
        }
    } else {
        for (int k = 0; k < cnt; k++) accum(nbr[start + k], wgt[start + k]);
    }

    // K = S^T S (symmetric)
    float K[3][3];
    K[0][0] = S00 * S00 + S10 * S10 + S20 * S20;
    K[0][1] = S00 * S01 + S10 * S11 + S20 * S21;
    K[0][2] = S00 * S02 + S10 * S12 + S20 * S22;
    K[1][1] = S01 * S01 + S11 * S11 + S21 * S21;
    K[1][2] = S01 * S02 + S11 * S12 + S21 * S22;
    K[2][2] = S02 * S02 + S12 * S12 + S22 * S22;
    K[1][0] = K[0][1]; K[2][0] = K[0][2]; K[2][1] = K[1][2];

    float V[3][3] = {{1.f, 0.f, 0.f}, {0.f, 1.f, 0.f}, {0.f, 0.f, 1.f}};

#pragma unroll
    for (int sweep = 0; sweep < 4; sweep++) {
        jrot<0, 1>(K, V);
        jrot<1, 2>(K, V);
        jrot<0, 2>(K, V);
    }

    // Sort eigenpairs descending (columns of V follow eigenvalues)
    float l0 = K[0][0], l1 = K[1][1], l2 = K[2][2];
    float t;
    if (l0 < l1) {
        t = l0; l0 = l1; l1 = t;
        t = V[0][0]; V[0][0] = V[0][1]; V[0][1] = t;
        t = V[1][0]; V[1][0] = V[1][1]; V[1][1] = t;
        t = V[2][0]; V[2][0] = V[2][1]; V[2][1] = t;
    }
    if (l0 < l2) {
        t = l0; l0 = l2; l2 = t;
        t = V[0][0]; V[0][0] = V[0][2]; V[0][2] = t;
        t = V[1][0]; V[1][0] = V[1][2]; V[1][2] = t;
        t = V[2][0]; V[2][0] = V[2][2]; V[2][2] = t;
    }
    if (l1 < l2) {
        t = l1; l1 = l2; l2 = t;
        t = V[0][1]; V[0][1] = V[0][2]; V[0][2] = t;
        t = V[1][1]; V[1][1] = V[1][2]; V[1][2] = t;
        t = V[2][1]; V[2][1] = V[2][2]; V[2][2] = t;
    }

    // Force det(V) = +1 (flip column of smallest eigenvalue; matches the
    // reference's reflection fix on the smallest singular direction).
    {
        float cx = V[1][1] * V[2][2] - V[2][1] * V[1][2];
        float cy = V[2][1] * V[0][2] - V[0][1] * V[2][2];
        float cz = V[0][1] * V[1][2] - V[1][1] * V[0][2];
        float det = V[0][0] * cx + V[1][0] * cy + V[2][0] * cz;
        if (det < 0.f) { V[0][2] = -V[0][2]; V[1][2] = -V[1][2]; V[2][2] = -V[2][2]; }
    }

    // U columns: u0 = S v0 / |S v0|, u1 = S v1 / |S v1|, u2 = u0 x u1
    float b0x = S00 * V[0][0] + S01 * V[1][0] + S02 * V[2][0];
    float b0y = S10 * V[0][0] + S11 * V[1][0] + S12 * V[2][0];
    float b0z = S20 * V[0][0] + S21 * V[1][0] + S22 * V[2][0];
    float b1x = S00 * V[0][1] + S01 * V[1][1] + S02 * V[2][1];
    float b1y = S10 * V[0][1] + S11 * V[1][1] + S12 * V[2][1];
    float b1z = S20 * V[0][1] + S21 * V[1][1] + S22 * V[2][1];

    float r0 = rsqrtf(b0x * b0x + b0y * b0y + b0z * b0z);
    float u0x = b0x * r0, u0y = b0y * r0, u0z = b0z * r0;
    float r1 = rsqrtf(b1x * b1x + b1y * b1y + b1z * b1z);
    float u1x = b1x * r1, u1y = b1y * r1, u1z = b1z * r1;
    float u2x = u0y * u1z - u0z * u1y;
    float u2y = u0z * u1x - u0x * u1z;
    float u2z = u0x * u1y - u0y * u1x;

    // R = V U^T, row-major
    float* o = out + (size_t)(vbase + i) * 9;
    o[0] = V[0][0] * u0x + V[0][1] * u1x + V[0][2] * u2x;
    o[1] = V[0][0] * u0y + V[0][1] * u1y + V[0][2] * u2y;
    o[2] = V[0][0] * u0z + V[0][1] * u1z + V[0][2] * u2z;
    o[3] = V[1][0] * u0x + V[1][1] * u1x + V[1][2] * u2x;
    o[4] = V[1][0] * u0y + V[1][1] * u1y + V[1][2] * u2y;
    o[5] = V[1][0] * u0z + V[1][1] * u1z + V[1][2] * u2z;
    o[6] = V[2][0] * u0x + V[2][1] * u1x + V[2][2] * u2x;
    o[7] = V[2][0] * u0y + V[2][1] * u1y + V[2][2] * u2y;
    o[8] = V[2][0] * u0z + V[2][1] * u1z + V[2][2] * u2z;
}

// ---------------------------------------------------------------------------
// Inputs (metadata order): xyz1, xyz2, neighborList, numNeighbors,
// accnumNeighbors, weightMatrix, rotations, arapWeight
// ---------------------------------------------------------------------------
extern "C" void kernel_launch(void* const* d_in, const int* in_sizes, int n_in,
                              void* d_out, int out_size) {
    const float* xyz1 = (const float*)d_in[0];
    const float* xyz2 = (const float*)d_in[1];
    const int* nbr = (const int*)d_in[2];
    const int* numN = (const int*)d_in[3];
    const int* accN = (const int*)d_in[4];
    const float* wgt = (const float*)d_in[5];
    float* out = (float*)d_out;

    int n = in_sizes[3];                 // N vertices
    int b = in_sizes[0] / (3 * n);       // batches
    int npts = b * n;

    pack_kernel<<<(npts + 255) / 256, 256>>>(xyz1, xyz2, npts);

    dim3 grid((n + 255) / 256, b);
    arap_rot_kernel<<<grid, 256>>>(nbr, numN, accN, wgt, out, n);
}